// round 17
// baseline (speedup 1.0000x reference)
#include <cuda_runtime.h>

// Problem constants (fixed by the reference)
#define BB   4
#define DD   512
#define NN   4096
#define HH   16      // heads
#define HD   32      // head dim
#define KK   9       // kernel taps
#define DIL  3
#define PADW 12      // DIL*(KK-1)/2
#define TILE 256
#define SPAN (TILE + 2 * PADW)   // 280, multiple of 4
#define NTHREADS 256
#define CHUNK 16                 // output channels per round
#define OPAD 17                  // CHUNK + 1 (bank-conflict pad)

// Stage one [HD][SPAN] channel-tile (with zero-filled halo) into SMEM.
__device__ __forceinline__ void stage_tile(float* __restrict__ dst,
                                           const float* __restrict__ src,
                                           int g0, bool interior, int tid) {
    if (interior) {
        // float4 path: g0 = n0-12 with n0 % 256 == 0 -> 16B aligned
        const int NV = HD * (SPAN / 4);  // 2240 float4s
        #pragma unroll
        for (int it = 0; it < (NV + NTHREADS - 1) / NTHREADS; ++it) {
            int j = tid + it * NTHREADS;
            if (j < NV) {
                int c  = j / (SPAN / 4);
                int p4 = j - c * (SPAN / 4);
                *(float4*)(dst + c * SPAN + p4 * 4) =
                    *(const float4*)(src + (size_t)c * NN + g0 + p4 * 4);
            }
        }
    } else {
        for (int j = tid; j < HD * SPAN; j += NTHREADS) {
            int c = j / SPAN;
            int p = j - c * SPAN;
            int g = g0 + p;
            bool ok = (g >= 0) && (g < NN);
            dst[c * SPAN + p] = ok ? src[(size_t)c * NN + g] : 0.0f;
        }
    }
}

__global__ __launch_bounds__(NTHREADS, 4)
void dilattn_kernel(const float* __restrict__ q,
                    const float* __restrict__ k,
                    const float* __restrict__ v,
                    float* __restrict__ out) {
    extern __shared__ float smem[];
    float* buf  = smem;                 // [HD][SPAN]  (k, then v)
    float* outS = smem + HD * SPAN;     // [TILE][OPAD] channel-chunk staging

    const int tid  = threadIdx.x;
    const int tile = blockIdx.x;
    const int h    = blockIdx.y;
    const int b    = blockIdx.z;
    const int n0   = tile * TILE;
    const int g0   = n0 - PADW;
    const bool interior = (g0 >= 0) && (g0 + SPAN <= NN);

    const size_t chan_base = ((size_t)b * DD + (size_t)h * HD) * NN;

    // ---- Phase 1: stage K tile, compute logits ----
    stage_tile(buf, k + chan_base, g0, interior, tid);
    __syncthreads();

    float att[KK];
    #pragma unroll
    for (int j = 0; j < KK; ++j) att[j] = 0.0f;

    const float* qg = q + chan_base + (size_t)(n0 + tid);
    #pragma unroll
    for (int c = 0; c < HD; ++c) {
        float qc = __ldg(qg + (size_t)c * NN);
        #pragma unroll
        for (int j = 0; j < KK; ++j)
            att[j] += qc * buf[c * SPAN + tid + 3 * j];
    }

    // ---- Softmax over the 9 taps (scale folded into exp arg) ----
    const float scale = 0.17677669529663687f;  // 32^-0.5
    float m = att[0];
    #pragma unroll
    for (int j = 1; j < KK; ++j) m = fmaxf(m, att[j]);
    float s = 0.0f;
    #pragma unroll
    for (int j = 0; j < KK; ++j) {
        att[j] = __expf((att[j] - m) * scale);
        s += att[j];
    }
    const float inv = 1.0f / s;
    #pragma unroll
    for (int j = 0; j < KK; ++j) att[j] *= inv;

    // ---- Phase 2: stage V tile (overwrite k buffer), compute outputs ----
    __syncthreads();  // all k reads done
    stage_tile(buf, v + chan_base, g0, interior, tid);
    __syncthreads();

    float* og = out + ((size_t)b * NN + (size_t)n0) * DD + (size_t)h * HD;
    const int wid  = tid >> 5;
    const int lane = tid & 31;
    const int th   = lane >> 4;    // token-half within warp
    const int lh   = lane & 15;    // channel within chunk

    #pragma unroll
    for (int round = 0; round < HD / CHUNK; ++round) {
        // compute CHUNK channels for this thread's token into SMEM
        #pragma unroll
        for (int cc = 0; cc < CHUNK; ++cc) {
            const float* vrow = buf + (round * CHUNK + cc) * SPAN + tid;
            float acc = 0.0f;
            #pragma unroll
            for (int j = 0; j < KK; ++j)
                acc += att[j] * vrow[3 * j];
            outS[tid * OPAD + cc] = acc;
        }
        __syncthreads();

        // coalesced store: each warp writes 2 tokens x 64B per iteration
        #pragma unroll
        for (int it = 0; it < TILE / 16; ++it) {
            int token = 2 * wid + th + 16 * it;
            og[(size_t)token * DD + round * CHUNK + lh] = outS[token * OPAD + lh];
        }
        __syncthreads();
    }
}

extern "C" void kernel_launch(void* const* d_in, const int* in_sizes, int n_in,
                              void* d_out, int out_size) {
    const float* q = (const float*)d_in[0];
    const float* k = (const float*)d_in[1];
    const float* v = (const float*)d_in[2];
    float* out = (float*)d_out;

    const size_t smem_bytes =
        (size_t)(HD * SPAN + TILE * OPAD) * sizeof(float);  // 35,840 + 17,408 = 53,248 B
    cudaFuncSetAttribute(dilattn_kernel,
                         cudaFuncAttributeMaxDynamicSharedMemorySize,
                         (int)smem_bytes);

    dim3 grid(NN / TILE, HH, BB);  // (16, 16, 4) = 1024 CTAs
    dilattn_kernel<<<grid, NTHREADS, smem_bytes>>>(q, k, v, out);
}